// round 15
// baseline (speedup 1.0000x reference)
#include <cuda_runtime.h>
#include <cuda_bf16.h>
#include <math.h>
#include <stdint.h>

#define BSZ     2
#define LSEQ    2048
#define DMODEL  1024
#define DINNER  2048
#define NSTATE  16
#define KCONV   4
#define NTOK    (BSZ*LSEQ)   // 4096

// ---------------- scratch (static device globals; no allocation) -------------
__device__ __align__(256) __nv_bfloat16 g_hbf   [NTOK*DMODEL];
__device__ __align__(256) __nv_bfloat16 g_xsbf  [NTOK*DINNER];
__device__ __align__(256) __nv_bfloat16 g_gatebf[NTOK*DINNER];
__device__ __align__(256) __nv_bfloat16 g_xcbf  [NTOK*DINNER];
__device__ __align__(256) __nv_bfloat16 g_ybf   [NTOK*DINNER];
__device__ __align__(256) __nv_bfloat16 g_Wint  [(2*DINNER)*DMODEL];
__device__ __align__(256) __nv_bfloat16 g_Wdt   [DINNER*DINNER];
__device__ __align__(256) __nv_bfloat16 g_Woutt [DMODEL*DINNER];
__device__ __align__(256) __nv_bfloat16 g_Bbf   [NSTATE*DINNER];
__device__ float g_dsum[NTOK];
__device__ float g_BxRaw[NTOK*NSTATE];
__device__ float g_hs  [NTOK*NSTATE];

// ---------------- helpers ----------------------------------------------------
__device__ __forceinline__ uint32_t smem_u32(const void* p) {
    uint32_t a;
    asm("{ .reg .u64 t; cvta.to.shared.u64 t, %1; cvt.u32.u64 %0, t; }" : "=r"(a) : "l"(p));
    return a;
}
__device__ __forceinline__ void cp16(uint32_t saddr, const void* g) {
    asm volatile("cp.async.cg.shared.global [%0], [%1], 16;" :: "r"(saddr), "l"(g) : "memory");
}
#define CP_COMMIT() asm volatile("cp.async.commit_group;" ::: "memory")

__device__ __forceinline__ void ldsm_x4(uint32_t& r0, uint32_t& r1, uint32_t& r2, uint32_t& r3,
                                        uint32_t addr) {
    asm volatile("ldmatrix.sync.aligned.m8n8.x4.shared.b16 {%0,%1,%2,%3}, [%4];"
                 : "=r"(r0), "=r"(r1), "=r"(r2), "=r"(r3) : "r"(addr));
}
__device__ __forceinline__ void mma_bf16(float& c0, float& c1, float& c2, float& c3,
                                         uint32_t a0, uint32_t a1, uint32_t a2, uint32_t a3,
                                         uint32_t b0, uint32_t b1) {
    asm volatile("mma.sync.aligned.m16n8k16.row.col.f32.bf16.bf16.f32 "
                 "{%0,%1,%2,%3}, {%4,%5,%6,%7}, {%8,%9}, {%0,%1,%2,%3};"
                 : "+f"(c0), "+f"(c1), "+f"(c2), "+f"(c3)
                 : "r"(a0), "r"(a1), "r"(a2), "r"(a3), "r"(b0), "r"(b1));
}
__device__ __forceinline__ float fsigmoid(float v) { return 1.f / (1.f + __expf(-v)); }
__device__ __forceinline__ float fsoftplus(float v) {
    return (v > 20.f) ? v : __logf(1.f + __expf(v));
}

// ---------------- weight transpose tile body ---------------------------------
__device__ __forceinline__ void wtrans_tile(const float* __restrict__ src,
                                            __nv_bfloat16* __restrict__ dst,
                                            int R, int C, int bx, int by) {
    __shared__ float t[32][33];
    int txi = threadIdx.x & 31, tyi = threadIdx.x >> 5;
    int x = bx * 32 + txi;
    int y0 = by * 32;
#pragma unroll
    for (int j = 0; j < 32; j += 8)
        t[tyi + j][txi] = src[(size_t)(y0 + tyi + j) * C + x];
    __syncthreads();
    int xo = by * 32 + txi;
    int yo0 = bx * 32;
#pragma unroll
    for (int j = 0; j < 32; j += 8)
        dst[(size_t)(yo0 + tyi + j) * R + xo] = __float2bfloat16_rn(t[txi][tyi + j]);
}

__global__ __launch_bounds__(256) void wtrans_kernel(const float* __restrict__ src,
                                                     __nv_bfloat16* __restrict__ dst,
                                                     int R, int C) {
    wtrans_tile(src, dst, R, C, blockIdx.x, blockIdx.y);
}

// combined prep: Wd transpose + Wout transpose + bconv
#define WD_TILES   (64 * 64)
#define WOUT_TILES (32 * 64)
__global__ __launch_bounds__(256) void prep_kernel(const float* __restrict__ Wd,
                                                   const float* __restrict__ Wout,
                                                   const float* __restrict__ Bmat) {
    int b = blockIdx.x;
    if (b < WD_TILES) {
        wtrans_tile(Wd, g_Wdt, DINNER, DINNER, b & 63, b >> 6);
    } else if (b < WD_TILES + WOUT_TILES) {
        int bb = b - WD_TILES;
        wtrans_tile(Wout, g_Woutt, DINNER, DMODEL, bb & 31, bb >> 5);
    } else {
        int bb = b - WD_TILES - WOUT_TILES;
        int i = bb * 256 + threadIdx.x;
        float2 v = *(const float2*)(Bmat + 2 * i);
        *(__nv_bfloat162*)(g_Bbf + 2 * i) = __floats2bfloat162_rn(v.x, v.y);
    }
}

// ---------------- layernorm (writes bf16) + zeroes g_dsum --------------------
__global__ __launch_bounds__(256) void ln_kernel(const float* __restrict__ x,
                                                 const float* __restrict__ gamma,
                                                 const float* __restrict__ beta) {
    int row = blockIdx.x;
    if (threadIdx.x == 0) g_dsum[row] = 0.f;
    const float* xr = x + (size_t)row * DMODEL;
    float v[4];
    float s = 0.f, s2 = 0.f;
#pragma unroll
    for (int i = 0; i < 4; i++) {
        v[i] = xr[threadIdx.x + i * 256];
        s  += v[i];
        s2 += v[i] * v[i];
    }
    __shared__ float shs[8], shs2[8];
#pragma unroll
    for (int off = 16; off > 0; off >>= 1) {
        s  += __shfl_xor_sync(0xffffffffu, s,  off);
        s2 += __shfl_xor_sync(0xffffffffu, s2, off);
    }
    int warp = threadIdx.x >> 5, lane = threadIdx.x & 31;
    if (lane == 0) { shs[warp] = s; shs2[warp] = s2; }
    __syncthreads();
    if (threadIdx.x == 0) {
        float a = 0.f, b = 0.f;
#pragma unroll
        for (int w = 0; w < 8; w++) { a += shs[w]; b += shs2[w]; }
        shs[0] = a; shs2[0] = b;
    }
    __syncthreads();
    float mu  = shs[0]  * (1.f / DMODEL);
    float var = shs2[0] * (1.f / DMODEL) - mu * mu;
    float rs  = rsqrtf(var + 1e-5f);
    __nv_bfloat16* hr = g_hbf + (size_t)row * DMODEL;
#pragma unroll
    for (int i = 0; i < 4; i++) {
        int idx = threadIdx.x + i * 256;
        hr[idx] = __float2bfloat16_rn((v[i] - mu) * rs * gamma[idx] + beta[idx]);
    }
}

// ---------------- bf16 mma.sync GEMM, 3-stage pipeline (frozen config) -------
// row_base: global row offset for epilogue (A pointer pre-offset by caller).
#define ASTR 72
#define TILE_B (128 * ASTR * 2)
#define GSMEM_BYTES (6 * TILE_B)

template <int EPI>
__global__ __launch_bounds__(256) void mma_gemm(const __nv_bfloat16* __restrict__ A,
                                                const __nv_bfloat16* __restrict__ Bm,
                                                float* __restrict__ C0,
                                                const float* __restrict__ extra,
                                                const float* __restrict__ bias,
                                                int M, int N, int K, int row_base) {
    extern __shared__ char dsm[];
    uint32_t sb = smem_u32(dsm);

    int tid = threadIdx.x;
    int lane = tid & 31, wid = tid >> 5;
    int warp_m = wid & 1, warp_n = wid >> 1;
    int br = blockIdx.y, bc = blockIdx.x;

    const __nv_bfloat16* Ab = A + (size_t)(br * 128) * K;
    const __nv_bfloat16* Bb = Bm + (size_t)(bc * 128) * K;

    float acc[4][4][4];
#pragma unroll
    for (int mf = 0; mf < 4; mf++)
#pragma unroll
        for (int nf = 0; nf < 4; nf++)
#pragma unroll
            for (int j = 0; j < 4; j++) acc[mf][nf][j] = 0.f;

    int niter = K / 64;

#pragma unroll
    for (int st = 0; st < 2; ++st) {
        uint32_t sa = sb + st * TILE_B;
        uint32_t sbf = sb + (3 + st) * TILE_B;
        int kk = st * 64;
#pragma unroll
        for (int i = 0; i < 4; i++) {
            int idx = tid + i * 256;
            int row = idx >> 3, c = idx & 7;
            cp16(sa + row * (ASTR * 2) + c * 16, Ab + (size_t)row * K + kk + c * 8);
        }
#pragma unroll
        for (int i = 0; i < 4; i++) {
            int idx = tid + i * 256;
            int row = idx >> 3, c = idx & 7;
            cp16(sbf + row * (ASTR * 2) + c * 16, Bb + (size_t)row * K + kk + c * 8);
        }
        CP_COMMIT();
    }

    for (int it = 0; it < niter; ++it) {
        if (it + 2 < niter)
            asm volatile("cp.async.wait_group 1;" ::: "memory");
        else
            asm volatile("cp.async.wait_group 0;" ::: "memory");
        __syncthreads();

        if (it + 2 < niter) {
            int st = (it + 2) % 3;
            uint32_t sa = sb + st * TILE_B;
            uint32_t sbf = sb + (3 + st) * TILE_B;
            int kk = (it + 2) * 64;
#pragma unroll
            for (int i = 0; i < 4; i++) {
                int idx = tid + i * 256;
                int row = idx >> 3, c = idx & 7;
                cp16(sa + row * (ASTR * 2) + c * 16, Ab + (size_t)row * K + kk + c * 8);
            }
#pragma unroll
            for (int i = 0; i < 4; i++) {
                int idx = tid + i * 256;
                int row = idx >> 3, c = idx & 7;
                cp16(sbf + row * (ASTR * 2) + c * 16, Bb + (size_t)row * K + kk + c * 8);
            }
            CP_COMMIT();
        }

        int st = it % 3;
        uint32_t As = sb + st * TILE_B;
        uint32_t Bs = sb + (3 + st) * TILE_B;

#pragma unroll
        for (int ks = 0; ks < 4; ks++) {
            int k0 = ks * 16;
            uint32_t afr[4][4];
#pragma unroll
            for (int mf = 0; mf < 4; mf++) {
                int r = warp_m * 64 + mf * 16 + (lane & 15);
                uint32_t ad = As + (r * ASTR + k0 + (lane >> 4) * 8) * 2;
                ldsm_x4(afr[mf][0], afr[mf][1], afr[mf][2], afr[mf][3], ad);
            }
            uint32_t bfr[4][2];
#pragma unroll
            for (int nfp = 0; nfp < 2; nfp++) {
                int gsel = lane >> 3, rr = lane & 7;
                int n = warp_n * 32 + nfp * 16 + (gsel >> 1) * 8 + rr;
                int ko = k0 + (gsel & 1) * 8;
                uint32_t bd = Bs + (n * ASTR + ko) * 2;
                ldsm_x4(bfr[2 * nfp][0], bfr[2 * nfp][1],
                        bfr[2 * nfp + 1][0], bfr[2 * nfp + 1][1], bd);
            }
#pragma unroll
            for (int mf = 0; mf < 4; mf++)
#pragma unroll
                for (int nf = 0; nf < 4; nf++)
                    mma_bf16(acc[mf][nf][0], acc[mf][nf][1], acc[mf][nf][2], acc[mf][nf][3],
                             afr[mf][0], afr[mf][1], afr[mf][2], afr[mf][3],
                             bfr[nf][0], bfr[nf][1]);
        }
    }

    // -------- epilogue --------
    int g = lane >> 2, t4 = lane & 3;
#pragma unroll
    for (int mf = 0; mf < 4; mf++) {
        int row0 = row_base + br * 128 + warp_m * 64 + mf * 16 + g;
        if (EPI == 1) {
            float sum0 = 0.f, sum1 = 0.f;
#pragma unroll
            for (int nf = 0; nf < 4; nf++) {
                int col = bc * 128 + warp_n * 32 + nf * 8 + 2 * t4;
                float b0 = bias[col], b1 = bias[col + 1];
                sum0 += fsoftplus(acc[mf][nf][0] + b0);
                sum0 += fsoftplus(acc[mf][nf][1] + b1);
                sum1 += fsoftplus(acc[mf][nf][2] + b0);
                sum1 += fsoftplus(acc[mf][nf][3] + b1);
            }
#pragma unroll
            for (int off = 1; off < 4; off <<= 1) {
                sum0 += __shfl_xor_sync(0xffffffffu, sum0, off);
                sum1 += __shfl_xor_sync(0xffffffffu, sum1, off);
            }
            if (t4 == 0) {
                atomicAdd(&g_dsum[row0], sum0);
                atomicAdd(&g_dsum[row0 + 8], sum1);
            }
        } else if (EPI == 0) {
            bool left = (bc * 128 < DINNER);
            __nv_bfloat16* dst = left ? g_xsbf : g_gatebf;
            int cbase = bc * 128 - (left ? 0 : DINNER) + warp_n * 32;
#pragma unroll
            for (int nf = 0; nf < 4; nf++) {
                int col = cbase + nf * 8 + 2 * t4;
                *(__nv_bfloat162*)(dst + (size_t)row0 * DINNER + col) =
                    __floats2bfloat162_rn(acc[mf][nf][0], acc[mf][nf][1]);
                *(__nv_bfloat162*)(dst + (size_t)(row0 + 8) * DINNER + col) =
                    __floats2bfloat162_rn(acc[mf][nf][2], acc[mf][nf][3]);
            }
        } else {
#pragma unroll
            for (int nf = 0; nf < 4; nf++) {
                int col = bc * 128 + warp_n * 32 + nf * 8 + 2 * t4;
                float2 e0 = *(const float2*)(extra + (size_t)row0 * N + col);
                float2 e1 = *(const float2*)(extra + (size_t)(row0 + 8) * N + col);
                *(float2*)(C0 + (size_t)row0 * N + col) =
                    make_float2(acc[mf][nf][0] + e0.x, acc[mf][nf][1] + e0.y);
                *(float2*)(C0 + (size_t)(row0 + 8) * N + col) =
                    make_float2(acc[mf][nf][2] + e1.x, acc[mf][nf][3] + e1.y);
            }
        }
    }
}

// ---------------- fused conv+SiLU+B-dot: FOUR tokens per block ---------------
#define CB_TB 4
__global__ __launch_bounds__(256) void conv_bx_kernel(const float* __restrict__ w,
                                                      const float* __restrict__ cb,
                                                      int tok_base) {
    int t0 = tok_base + blockIdx.x * CB_TB;
    int b = t0 >> 11, l0 = t0 & (LSEQ - 1);
    int tid = threadIdx.x;
    int d = tid * 8;

    float4 wj[8];
    float cbv[8];
#pragma unroll
    for (int j = 0; j < 8; j++) {
        wj[j] = *(const float4*)(w + (d + j) * KCONV);
        cbv[j] = cb[d + j];
    }

    float xc[CB_TB][8];
#pragma unroll
    for (int tok = 0; tok < CB_TB; tok++) {
        int l = l0 + tok;
        float v[8];
#pragma unroll
        for (int j = 0; j < 8; j++) v[j] = cbv[j];
#pragma unroll
        for (int k = 0; k < KCONV; k++) {
            int ll = l - (KCONV - 1) + k;
            if (ll >= 0) {
                uint4 raw = *(const uint4*)(g_xsbf + ((size_t)(b * LSEQ + ll)) * DINNER + d);
                const __nv_bfloat162* p = (const __nv_bfloat162*)&raw;
#pragma unroll
                for (int j = 0; j < 4; j++) {
                    float2 f = __bfloat1622float2(p[j]);
                    float wk0 = (k == 0) ? wj[2 * j].x : (k == 1) ? wj[2 * j].y : (k == 2) ? wj[2 * j].z : wj[2 * j].w;
                    float wk1 = (k == 0) ? wj[2 * j + 1].x : (k == 1) ? wj[2 * j + 1].y : (k == 2) ? wj[2 * j + 1].z : wj[2 * j + 1].w;
                    v[2 * j]     = fmaf(wk0, f.x, v[2 * j]);
                    v[2 * j + 1] = fmaf(wk1, f.y, v[2 * j + 1]);
                }
            }
        }
        __nv_bfloat16 outv[8];
#pragma unroll
        for (int j = 0; j < 8; j++) {
            float s = v[j] * fsigmoid(v[j]);
            xc[tok][j] = s;
            outv[j] = __float2bfloat16_rn(s);
        }
        *(uint4*)(g_xcbf + (size_t)(t0 + tok) * DINNER + d) = *(uint4*)(outv);
    }

    __shared__ float sh[NSTATE][CB_TB][8];
    int warp = tid >> 5, lane = tid & 31;
#pragma unroll
    for (int n = 0; n < NSTATE; n++) {
        uint4 braw = *(const uint4*)(g_Bbf + n * DINNER + d);
        const __nv_bfloat162* p = (const __nv_bfloat162*)&braw;
        float bf[8];
#pragma unroll
        for (int j = 0; j < 4; j++) {
            float2 f = __bfloat1622float2(p[j]);
            bf[2 * j] = f.x; bf[2 * j + 1] = f.y;
        }
        float part[CB_TB];
#pragma unroll
        for (int tok = 0; tok < CB_TB; tok++) {
            float s = 0.f;
#pragma unroll
            for (int j = 0; j < 8; j++) s = fmaf(xc[tok][j], bf[j], s);
            part[tok] = s;
        }
#pragma unroll
        for (int tok = 0; tok < CB_TB; tok++)
#pragma unroll
            for (int off = 16; off > 0; off >>= 1)
                part[tok] += __shfl_xor_sync(0xffffffffu, part[tok], off);
        if (lane == 0)
#pragma unroll
            for (int tok = 0; tok < CB_TB; tok++) sh[n][tok][warp] = part[tok];
    }
    __syncthreads();
    if (tid < NSTATE * CB_TB) {
        int n = tid & 15, tok = tid >> 4;
        float tot = 0.f;
#pragma unroll
        for (int w8 = 0; w8 < 8; w8++) tot += sh[n][tok][w8];
        g_BxRaw[(size_t)(t0 + tok) * NSTATE + n] = tot;
    }
}

// ---------------- parallel scan; applies delta + dA inline -------------------
__global__ __launch_bounds__(256) void scan_kernel(const float* __restrict__ A_log) {
    int bn = blockIdx.x;
    int b = bn >> 4, n = bn & 15;
    size_t base = (size_t)b * LSEQ * NSTATE + n;
    int tid = threadIdx.x;
    int l0 = tid * 8;
    float An = -expf(A_log[n]);

    float av[8], bv[8];
#pragma unroll
    for (int i = 0; i < 8; i++) {
        int tok = b * LSEQ + l0 + i;
        float delta = g_dsum[tok] * (1.f / DINNER);
        av[i] = __expf(delta * An);
        bv[i] = g_BxRaw[(size_t)tok * NSTATE + n] * delta;
    }
    float aL = 1.f, bL = 0.f;
#pragma unroll
    for (int i = 0; i < 8; i++) { bL = fmaf(av[i], bL, bv[i]); aL *= av[i]; }

    __shared__ float sa[256], sbm[256];
    sa[tid] = aL; sbm[tid] = bL;
    __syncthreads();
#pragma unroll
    for (int off = 1; off < 256; off <<= 1) {
        float pa = 1.f, pb = 0.f;
        if (tid >= off) { pa = sa[tid - off]; pb = sbm[tid - off]; }
        float ca = sa[tid], cb2 = sbm[tid];
        __syncthreads();
        sa[tid] = pa * ca;
        sbm[tid] = fmaf(pb, ca, cb2);
        __syncthreads();
    }
    float h = (tid == 0) ? 0.f : sbm[tid - 1];
#pragma unroll
    for (int i = 0; i < 8; i++) {
        h = fmaf(av[i], h, bv[i]);
        g_hs[base + (size_t)(l0 + i) * NSTATE] = h;
    }
}

// ---------------- y = (hs@C^T + D*xc) * silu(gate), 8 tokens/block -----------
#define YM_TB 8
__global__ __launch_bounds__(256) void ymix_kernel(const float* __restrict__ Cmat,
                                                   const float* __restrict__ Dv,
                                                   int tok_base) {
    int t0 = tok_base + blockIdx.x * YM_TB;
    __shared__ float hsh[YM_TB][NSTATE];
    if (threadIdx.x < YM_TB * NSTATE) {
        int t = threadIdx.x >> 4, n = threadIdx.x & 15;
        hsh[t][n] = g_hs[(t0 + t) * NSTATE + n];
    }
    __syncthreads();

    for (int d = threadIdx.x; d < DINNER; d += 256) {
        const float4* cr = (const float4*)(Cmat + (size_t)d * NSTATE);
        float4 c0 = cr[0], c1 = cr[1], c2 = cr[2], c3 = cr[3];
        float dvd = Dv[d];
#pragma unroll
        for (int t = 0; t < YM_TB; t++) {
            const float* hh = hsh[t];
            float s = 0.f;
            s = fmaf(hh[0],  c0.x, s); s = fmaf(hh[1],  c0.y, s);
            s = fmaf(hh[2],  c0.z, s); s = fmaf(hh[3],  c0.w, s);
            s = fmaf(hh[4],  c1.x, s); s = fmaf(hh[5],  c1.y, s);
            s = fmaf(hh[6],  c1.z, s); s = fmaf(hh[7],  c1.w, s);
            s = fmaf(hh[8],  c2.x, s); s = fmaf(hh[9],  c2.y, s);
            s = fmaf(hh[10], c2.z, s); s = fmaf(hh[11], c2.w, s);
            s = fmaf(hh[12], c3.x, s); s = fmaf(hh[13], c3.y, s);
            s = fmaf(hh[14], c3.z, s); s = fmaf(hh[15], c3.w, s);
            size_t idx = (size_t)(t0 + t) * DINNER + d;
            float xv = __bfloat162float(g_xcbf[idx]);
            float yv = fmaf(dvd, xv, s);
            float gg = __bfloat162float(g_gatebf[idx]);
            yv *= gg * fsigmoid(gg);
            g_ybf[idx] = __float2bfloat16_rn(yv);
        }
    }
}

// ---------------- launch -----------------------------------------------------
extern "C" void kernel_launch(void* const* d_in, const int* in_sizes, int n_in,
                              void* d_out, int out_size) {
    const float* x       = (const float*)d_in[0];
    const float* ln_g    = (const float*)d_in[1];
    const float* ln_b    = (const float*)d_in[2];
    const float* W_in    = (const float*)d_in[3];
    const float* conv_w  = (const float*)d_in[4];
    const float* conv_b  = (const float*)d_in[5];
    const float* A_log   = (const float*)d_in[6];
    const float* B_mat   = (const float*)d_in[7];
    const float* C_mat   = (const float*)d_in[8];
    const float* D_vec   = (const float*)d_in[9];
    const float* Wd      = (const float*)d_in[10];
    const float* bd      = (const float*)d_in[11];
    const float* W_out   = (const float*)d_in[12];
    float* out           = (float*)d_out;

    __nv_bfloat16 *hbf, *ybf, *wint, *wdt, *woutt, *xcbf;
    cudaGetSymbolAddress((void**)&hbf,   g_hbf);
    cudaGetSymbolAddress((void**)&ybf,   g_ybf);
    cudaGetSymbolAddress((void**)&wint,  g_Wint);
    cudaGetSymbolAddress((void**)&wdt,   g_Wdt);
    cudaGetSymbolAddress((void**)&woutt, g_Woutt);
    cudaGetSymbolAddress((void**)&xcbf,  g_xcbf);

    static cudaStream_t s1 = nullptr, s2 = nullptr;
    static cudaEvent_t ev[7] = {};
    static bool attr_done = false;
    if (!s1) {
        cudaStreamCreateWithFlags(&s1, cudaStreamNonBlocking);
        cudaStreamCreateWithFlags(&s2, cudaStreamNonBlocking);
        for (int i = 0; i < 7; i++) cudaEventCreateWithFlags(&ev[i], cudaEventDisableTiming);
    }
    if (!attr_done) {
        cudaFuncSetAttribute(mma_gemm<0>, cudaFuncAttributeMaxDynamicSharedMemorySize, GSMEM_BYTES);
        cudaFuncSetAttribute(mma_gemm<1>, cudaFuncAttributeMaxDynamicSharedMemorySize, GSMEM_BYTES);
        cudaFuncSetAttribute(mma_gemm<2>, cudaFuncAttributeMaxDynamicSharedMemorySize, GSMEM_BYTES);
        attr_done = true;
    }

    const int HALF = NTOK / 2;   // 2048 rows

    // fork
    cudaEventRecord(ev[0], 0);
    cudaStreamWaitEvent(s1, ev[0], 0);
    cudaStreamWaitEvent(s2, ev[0], 0);

    // s1: W_in transpose (GEMM1 dep)
    wtrans_kernel<<<dim3(2 * DINNER / 32, DMODEL / 32), 256, 0, s1>>>(W_in, wint, DMODEL, 2 * DINNER);
    cudaEventRecord(ev[1], s1);

    // s2: Wd/Wout transpose + B convert
    prep_kernel<<<WD_TILES + WOUT_TILES + 64, 256, 0, s2>>>(Wd, W_out, B_mat);
    cudaEventRecord(ev[2], s2);

    // main stream
    ln_kernel<<<NTOK, 256>>>(x, ln_g, ln_b);
    cudaStreamWaitEvent(0, ev[1], 0);
    // GEMM1 (full)
    mma_gemm<0><<<dim3(32, 32), 256, GSMEM_BYTES>>>(hbf, wint, nullptr, nullptr, nullptr,
                                                    NTOK, 2 * DINNER, DMODEL, 0);
    cudaStreamWaitEvent(0, ev[2], 0);
    // conv_bx half0, then GEMM2(h0) on s1 overlapping conv_bx half1 + GEMM2(h1)
    conv_bx_kernel<<<HALF / CB_TB, 256>>>(conv_w, conv_b, 0);
    cudaEventRecord(ev[3], 0);
    cudaStreamWaitEvent(s1, ev[3], 0);
    mma_gemm<1><<<dim3(16, 16), 256, GSMEM_BYTES, s1>>>(xcbf, wdt, nullptr, nullptr, bd,
                                                        NTOK, DINNER, DINNER, 0);
    cudaEventRecord(ev[4], s1);
    conv_bx_kernel<<<HALF / CB_TB, 256>>>(conv_w, conv_b, HALF);
    mma_gemm<1><<<dim3(16, 16), 256, GSMEM_BYTES>>>(xcbf + (size_t)HALF * DINNER, wdt,
                                                    nullptr, nullptr, bd,
                                                    NTOK, DINNER, DINNER, HALF);
    cudaStreamWaitEvent(0, ev[4], 0);   // both GEMM2 halves done before scan
    scan_kernel<<<BSZ * NSTATE, 256>>>(A_log);
    // ymix half0, then GEMM3(h0) on s1 overlapping ymix half1 + GEMM3(h1)
    ymix_kernel<<<HALF / YM_TB, 256>>>(C_mat, D_vec, 0);
    cudaEventRecord(ev[5], 0);
    cudaStreamWaitEvent(s1, ev[5], 0);
    mma_gemm<2><<<dim3(8, 16), 256, GSMEM_BYTES, s1>>>(ybf, woutt, out, x, nullptr,
                                                       NTOK, DMODEL, DINNER, 0);
    cudaEventRecord(ev[6], s1);
    ymix_kernel<<<HALF / YM_TB, 256>>>(C_mat, D_vec, HALF);
    mma_gemm<2><<<dim3(8, 16), 256, GSMEM_BYTES>>>(ybf + (size_t)HALF * DINNER, woutt,
                                                   out, x, nullptr,
                                                   NTOK, DMODEL, DINNER, HALF);
    cudaStreamWaitEvent(0, ev[6], 0);   // rejoin before capture ends
}

// round 16
// speedup vs baseline: 1.0765x; 1.0765x over previous
#include <cuda_runtime.h>
#include <cuda_bf16.h>
#include <math.h>
#include <stdint.h>

#define BSZ     2
#define LSEQ    2048
#define DMODEL  1024
#define DINNER  2048
#define NSTATE  16
#define KCONV   4
#define NTOK    (BSZ*LSEQ)   // 4096

// ---------------- scratch (static device globals; no allocation) -------------
__device__ __align__(256) __nv_bfloat16 g_hbf   [NTOK*DMODEL];
__device__ __align__(256) __nv_bfloat16 g_xsbf  [NTOK*DINNER];
__device__ __align__(256) __nv_bfloat16 g_gatebf[NTOK*DINNER];
__device__ __align__(256) __nv_bfloat16 g_xcbf  [NTOK*DINNER];
__device__ __align__(256) __nv_bfloat16 g_ybf   [NTOK*DINNER];
__device__ __align__(256) __nv_bfloat16 g_Wint  [(2*DINNER)*DMODEL];
__device__ __align__(256) __nv_bfloat16 g_Wdt   [DINNER*DINNER];
__device__ __align__(256) __nv_bfloat16 g_Woutt [DMODEL*DINNER];
__device__ __align__(256) __nv_bfloat16 g_Bbf   [NSTATE*DINNER];
__device__ float g_dsum[NTOK];
__device__ float g_BxRaw[NTOK*NSTATE];   // raw xc.B dots (pre-delta)
__device__ float g_hs  [NTOK*NSTATE];

// ---------------- helpers ----------------------------------------------------
__device__ __forceinline__ uint32_t smem_u32(const void* p) {
    uint32_t a;
    asm("{ .reg .u64 t; cvta.to.shared.u64 t, %1; cvt.u32.u64 %0, t; }" : "=r"(a) : "l"(p));
    return a;
}
__device__ __forceinline__ void cp16(uint32_t saddr, const void* g) {
    asm volatile("cp.async.cg.shared.global [%0], [%1], 16;" :: "r"(saddr), "l"(g) : "memory");
}
#define CP_COMMIT() asm volatile("cp.async.commit_group;" ::: "memory")

__device__ __forceinline__ void ldsm_x4(uint32_t& r0, uint32_t& r1, uint32_t& r2, uint32_t& r3,
                                        uint32_t addr) {
    asm volatile("ldmatrix.sync.aligned.m8n8.x4.shared.b16 {%0,%1,%2,%3}, [%4];"
                 : "=r"(r0), "=r"(r1), "=r"(r2), "=r"(r3) : "r"(addr));
}
__device__ __forceinline__ void mma_bf16(float& c0, float& c1, float& c2, float& c3,
                                         uint32_t a0, uint32_t a1, uint32_t a2, uint32_t a3,
                                         uint32_t b0, uint32_t b1) {
    asm volatile("mma.sync.aligned.m16n8k16.row.col.f32.bf16.bf16.f32 "
                 "{%0,%1,%2,%3}, {%4,%5,%6,%7}, {%8,%9}, {%0,%1,%2,%3};"
                 : "+f"(c0), "+f"(c1), "+f"(c2), "+f"(c3)
                 : "r"(a0), "r"(a1), "r"(a2), "r"(a3), "r"(b0), "r"(b1));
}
__device__ __forceinline__ float fsigmoid(float v) {
    return 1.f / (1.f + __expf(-v));
}
__device__ __forceinline__ float fsoftplus(float v) {
    return (v > 20.f) ? v : __logf(1.f + __expf(v));
}

// ---------------- weight transpose tile body ---------------------------------
__device__ __forceinline__ void wtrans_tile(const float* __restrict__ src,
                                            __nv_bfloat16* __restrict__ dst,
                                            int R, int C, int bx, int by) {
    __shared__ float t[32][33];
    int txi = threadIdx.x & 31, tyi = threadIdx.x >> 5;
    int x = bx * 32 + txi;
    int y0 = by * 32;
#pragma unroll
    for (int j = 0; j < 32; j += 8)
        t[tyi + j][txi] = src[(size_t)(y0 + tyi + j) * C + x];
    __syncthreads();
    int xo = by * 32 + txi;
    int yo0 = bx * 32;
#pragma unroll
    for (int j = 0; j < 32; j += 8)
        dst[(size_t)(yo0 + tyi + j) * R + xo] = __float2bfloat16_rn(t[txi][tyi + j]);
}

__global__ __launch_bounds__(256) void wtrans_kernel(const float* __restrict__ src,
                                                     __nv_bfloat16* __restrict__ dst,
                                                     int R, int C) {
    wtrans_tile(src, dst, R, C, blockIdx.x, blockIdx.y);
}

// combined prep: Wd transpose + Wout transpose + bconv
#define WD_TILES   (64 * 64)
#define WOUT_TILES (32 * 64)
__global__ __launch_bounds__(256) void prep_kernel(const float* __restrict__ Wd,
                                                   const float* __restrict__ Wout,
                                                   const float* __restrict__ Bmat) {
    int b = blockIdx.x;
    if (b < WD_TILES) {
        wtrans_tile(Wd, g_Wdt, DINNER, DINNER, b & 63, b >> 6);
    } else if (b < WD_TILES + WOUT_TILES) {
        int bb = b - WD_TILES;
        wtrans_tile(Wout, g_Woutt, DINNER, DMODEL, bb & 31, bb >> 5);
    } else {
        int bb = b - WD_TILES - WOUT_TILES;
        int i = bb * 256 + threadIdx.x;
        float2 v = *(const float2*)(Bmat + 2 * i);
        *(__nv_bfloat162*)(g_Bbf + 2 * i) = __floats2bfloat162_rn(v.x, v.y);
    }
}

// ---------------- layernorm (writes bf16) + zeroes g_dsum --------------------
__global__ __launch_bounds__(256) void ln_kernel(const float* __restrict__ x,
                                                 const float* __restrict__ gamma,
                                                 const float* __restrict__ beta) {
    int row = blockIdx.x;
    if (threadIdx.x == 0) g_dsum[row] = 0.f;
    const float* xr = x + (size_t)row * DMODEL;
    float v[4];
    float s = 0.f, s2 = 0.f;
#pragma unroll
    for (int i = 0; i < 4; i++) {
        v[i] = xr[threadIdx.x + i * 256];
        s  += v[i];
        s2 += v[i] * v[i];
    }
    __shared__ float shs[8], shs2[8];
#pragma unroll
    for (int off = 16; off > 0; off >>= 1) {
        s  += __shfl_xor_sync(0xffffffffu, s,  off);
        s2 += __shfl_xor_sync(0xffffffffu, s2, off);
    }
    int warp = threadIdx.x >> 5, lane = threadIdx.x & 31;
    if (lane == 0) { shs[warp] = s; shs2[warp] = s2; }
    __syncthreads();
    if (threadIdx.x == 0) {
        float a = 0.f, b = 0.f;
#pragma unroll
        for (int w = 0; w < 8; w++) { a += shs[w]; b += shs2[w]; }
        shs[0] = a; shs2[0] = b;
    }
    __syncthreads();
    float mu  = shs[0]  * (1.f / DMODEL);
    float var = shs2[0] * (1.f / DMODEL) - mu * mu;
    float rs  = rsqrtf(var + 1e-5f);
    __nv_bfloat16* hr = g_hbf + (size_t)row * DMODEL;
#pragma unroll
    for (int i = 0; i < 4; i++) {
        int idx = threadIdx.x + i * 256;
        hr[idx] = __float2bfloat16_rn((v[i] - mu) * rs * gamma[idx] + beta[idx]);
    }
}

// ---------------- bf16 mma.sync GEMM, 3-stage pipeline (frozen config) -------
#define ASTR 72
#define TILE_B (128 * ASTR * 2)
#define GSMEM_BYTES (6 * TILE_B)

template <int EPI>
__global__ __launch_bounds__(256) void mma_gemm(const __nv_bfloat16* __restrict__ A,
                                                const __nv_bfloat16* __restrict__ Bm,
                                                float* __restrict__ C0,
                                                const float* __restrict__ extra,
                                                const float* __restrict__ bias,
                                                int M, int N, int K) {
    extern __shared__ char dsm[];
    uint32_t sb = smem_u32(dsm);

    int tid = threadIdx.x;
    int lane = tid & 31, wid = tid >> 5;
    int warp_m = wid & 1, warp_n = wid >> 1;
    int br = blockIdx.y, bc = blockIdx.x;

    const __nv_bfloat16* Ab = A + (size_t)(br * 128) * K;
    const __nv_bfloat16* Bb = Bm + (size_t)(bc * 128) * K;

    float acc[4][4][4];
#pragma unroll
    for (int mf = 0; mf < 4; mf++)
#pragma unroll
        for (int nf = 0; nf < 4; nf++)
#pragma unroll
            for (int j = 0; j < 4; j++) acc[mf][nf][j] = 0.f;

    int niter = K / 64;

#pragma unroll
    for (int st = 0; st < 2; ++st) {
        uint32_t sa = sb + st * TILE_B;
        uint32_t sbf = sb + (3 + st) * TILE_B;
        int kk = st * 64;
#pragma unroll
        for (int i = 0; i < 4; i++) {
            int idx = tid + i * 256;
            int row = idx >> 3, c = idx & 7;
            cp16(sa + row * (ASTR * 2) + c * 16, Ab + (size_t)row * K + kk + c * 8);
        }
#pragma unroll
        for (int i = 0; i < 4; i++) {
            int idx = tid + i * 256;
            int row = idx >> 3, c = idx & 7;
            cp16(sbf + row * (ASTR * 2) + c * 16, Bb + (size_t)row * K + kk + c * 8);
        }
        CP_COMMIT();
    }

    for (int it = 0; it < niter; ++it) {
        if (it + 2 < niter)
            asm volatile("cp.async.wait_group 1;" ::: "memory");
        else
            asm volatile("cp.async.wait_group 0;" ::: "memory");
        __syncthreads();

        if (it + 2 < niter) {
            int st = (it + 2) % 3;
            uint32_t sa = sb + st * TILE_B;
            uint32_t sbf = sb + (3 + st) * TILE_B;
            int kk = (it + 2) * 64;
#pragma unroll
            for (int i = 0; i < 4; i++) {
                int idx = tid + i * 256;
                int row = idx >> 3, c = idx & 7;
                cp16(sa + row * (ASTR * 2) + c * 16, Ab + (size_t)row * K + kk + c * 8);
            }
#pragma unroll
            for (int i = 0; i < 4; i++) {
                int idx = tid + i * 256;
                int row = idx >> 3, c = idx & 7;
                cp16(sbf + row * (ASTR * 2) + c * 16, Bb + (size_t)row * K + kk + c * 8);
            }
            CP_COMMIT();
        }

        int st = it % 3;
        uint32_t As = sb + st * TILE_B;
        uint32_t Bs = sb + (3 + st) * TILE_B;

#pragma unroll
        for (int ks = 0; ks < 4; ks++) {
            int k0 = ks * 16;
            uint32_t afr[4][4];
#pragma unroll
            for (int mf = 0; mf < 4; mf++) {
                int r = warp_m * 64 + mf * 16 + (lane & 15);
                uint32_t ad = As + (r * ASTR + k0 + (lane >> 4) * 8) * 2;
                ldsm_x4(afr[mf][0], afr[mf][1], afr[mf][2], afr[mf][3], ad);
            }
            uint32_t bfr[4][2];
#pragma unroll
            for (int nfp = 0; nfp < 2; nfp++) {
                int gsel = lane >> 3, rr = lane & 7;
                int n = warp_n * 32 + nfp * 16 + (gsel >> 1) * 8 + rr;
                int ko = k0 + (gsel & 1) * 8;
                uint32_t bd = Bs + (n * ASTR + ko) * 2;
                ldsm_x4(bfr[2 * nfp][0], bfr[2 * nfp][1],
                        bfr[2 * nfp + 1][0], bfr[2 * nfp + 1][1], bd);
            }
#pragma unroll
            for (int mf = 0; mf < 4; mf++)
#pragma unroll
                for (int nf = 0; nf < 4; nf++)
                    mma_bf16(acc[mf][nf][0], acc[mf][nf][1], acc[mf][nf][2], acc[mf][nf][3],
                             afr[mf][0], afr[mf][1], afr[mf][2], afr[mf][3],
                             bfr[nf][0], bfr[nf][1]);
        }
    }

    // -------- epilogue --------
    int g = lane >> 2, t4 = lane & 3;
#pragma unroll
    for (int mf = 0; mf < 4; mf++) {
        int row0 = br * 128 + warp_m * 64 + mf * 16 + g;
        if (EPI == 1) {
            float sum0 = 0.f, sum1 = 0.f;
#pragma unroll
            for (int nf = 0; nf < 4; nf++) {
                int col = bc * 128 + warp_n * 32 + nf * 8 + 2 * t4;
                float b0 = bias[col], b1 = bias[col + 1];
                sum0 += fsoftplus(acc[mf][nf][0] + b0);
                sum0 += fsoftplus(acc[mf][nf][1] + b1);
                sum1 += fsoftplus(acc[mf][nf][2] + b0);
                sum1 += fsoftplus(acc[mf][nf][3] + b1);
            }
#pragma unroll
            for (int off = 1; off < 4; off <<= 1) {
                sum0 += __shfl_xor_sync(0xffffffffu, sum0, off);
                sum1 += __shfl_xor_sync(0xffffffffu, sum1, off);
            }
            if (t4 == 0) {
                atomicAdd(&g_dsum[row0], sum0);
                atomicAdd(&g_dsum[row0 + 8], sum1);
            }
        } else if (EPI == 0) {
            bool left = (bc * 128 < DINNER);
            __nv_bfloat16* dst = left ? g_xsbf : g_gatebf;
            int cbase = bc * 128 - (left ? 0 : DINNER) + warp_n * 32;
#pragma unroll
            for (int nf = 0; nf < 4; nf++) {
                int col = cbase + nf * 8 + 2 * t4;
                *(__nv_bfloat162*)(dst + (size_t)row0 * DINNER + col) =
                    __floats2bfloat162_rn(acc[mf][nf][0], acc[mf][nf][1]);
                *(__nv_bfloat162*)(dst + (size_t)(row0 + 8) * DINNER + col) =
                    __floats2bfloat162_rn(acc[mf][nf][2], acc[mf][nf][3]);
            }
        } else {
#pragma unroll
            for (int nf = 0; nf < 4; nf++) {
                int col = bc * 128 + warp_n * 32 + nf * 8 + 2 * t4;
                float2 e0 = *(const float2*)(extra + (size_t)row0 * N + col);
                float2 e1 = *(const float2*)(extra + (size_t)(row0 + 8) * N + col);
                *(float2*)(C0 + (size_t)row0 * N + col) =
                    make_float2(acc[mf][nf][0] + e0.x, acc[mf][nf][1] + e0.y);
                *(float2*)(C0 + (size_t)(row0 + 8) * N + col) =
                    make_float2(acc[mf][nf][2] + e1.x, acc[mf][nf][3] + e1.y);
            }
        }
    }
}

// ---------------- fused conv+SiLU+B-dot: FOUR tokens per block ---------------
#define CB_TB 4
__global__ __launch_bounds__(256) void conv_bx_kernel(const float* __restrict__ w,
                                                      const float* __restrict__ cb) {
    int t0 = blockIdx.x * CB_TB;
    int b = t0 >> 11, l0 = t0 & (LSEQ - 1);
    int tid = threadIdx.x;
    int d = tid * 8;

    float4 wj[8];
    float cbv[8];
#pragma unroll
    for (int j = 0; j < 8; j++) {
        wj[j] = *(const float4*)(w + (d + j) * KCONV);
        cbv[j] = cb[d + j];
    }

    float xc[CB_TB][8];
#pragma unroll
    for (int tok = 0; tok < CB_TB; tok++) {
        int l = l0 + tok;
        float v[8];
#pragma unroll
        for (int j = 0; j < 8; j++) v[j] = cbv[j];
#pragma unroll
        for (int k = 0; k < KCONV; k++) {
            int ll = l - (KCONV - 1) + k;
            if (ll >= 0) {
                uint4 raw = *(const uint4*)(g_xsbf + ((size_t)(b * LSEQ + ll)) * DINNER + d);
                const __nv_bfloat162* p = (const __nv_bfloat162*)&raw;
#pragma unroll
                for (int j = 0; j < 4; j++) {
                    float2 f = __bfloat1622float2(p[j]);
                    float wk0 = (k == 0) ? wj[2 * j].x : (k == 1) ? wj[2 * j].y : (k == 2) ? wj[2 * j].z : wj[2 * j].w;
                    float wk1 = (k == 0) ? wj[2 * j + 1].x : (k == 1) ? wj[2 * j + 1].y : (k == 2) ? wj[2 * j + 1].z : wj[2 * j + 1].w;
                    v[2 * j]     = fmaf(wk0, f.x, v[2 * j]);
                    v[2 * j + 1] = fmaf(wk1, f.y, v[2 * j + 1]);
                }
            }
        }
        __nv_bfloat16 outv[8];
#pragma unroll
        for (int j = 0; j < 8; j++) {
            float s = v[j] * fsigmoid(v[j]);
            xc[tok][j] = s;
            outv[j] = __float2bfloat16_rn(s);
        }
        *(uint4*)(g_xcbf + (size_t)(t0 + tok) * DINNER + d) = *(uint4*)(outv);
    }

    __shared__ float sh[NSTATE][CB_TB][8];
    int warp = tid >> 5, lane = tid & 31;
#pragma unroll
    for (int n = 0; n < NSTATE; n++) {
        uint4 braw = *(const uint4*)(g_Bbf + n * DINNER + d);
        const __nv_bfloat162* p = (const __nv_bfloat162*)&braw;
        float bf[8];
#pragma unroll
        for (int j = 0; j < 4; j++) {
            float2 f = __bfloat1622float2(p[j]);
            bf[2 * j] = f.x; bf[2 * j + 1] = f.y;
        }
        float part[CB_TB];
#pragma unroll
        for (int tok = 0; tok < CB_TB; tok++) {
            float s = 0.f;
#pragma unroll
            for (int j = 0; j < 8; j++) s = fmaf(xc[tok][j], bf[j], s);
            part[tok] = s;
        }
#pragma unroll
        for (int tok = 0; tok < CB_TB; tok++)
#pragma unroll
            for (int off = 16; off > 0; off >>= 1)
                part[tok] += __shfl_xor_sync(0xffffffffu, part[tok], off);
        if (lane == 0)
#pragma unroll
            for (int tok = 0; tok < CB_TB; tok++) sh[n][tok][warp] = part[tok];
    }
    __syncthreads();
    if (tid < NSTATE * CB_TB) {
        int n = tid & 15, tok = tid >> 4;
        float tot = 0.f;
#pragma unroll
        for (int w8 = 0; w8 < 8; w8++) tot += sh[n][tok][w8];
        g_BxRaw[(size_t)(t0 + tok) * NSTATE + n] = tot;
    }
}

// ---------------- parallel scan; applies delta + dA inline -------------------
__global__ __launch_bounds__(256) void scan_kernel(const float* __restrict__ A_log) {
    int bn = blockIdx.x;
    int b = bn >> 4, n = bn & 15;
    size_t base = (size_t)b * LSEQ * NSTATE + n;
    int tid = threadIdx.x;
    int l0 = tid * 8;
    float An = -expf(A_log[n]);

    float av[8], bv[8];
#pragma unroll
    for (int i = 0; i < 8; i++) {
        int tok = b * LSEQ + l0 + i;
        float delta = g_dsum[tok] * (1.f / DINNER);
        av[i] = __expf(delta * An);
        bv[i] = g_BxRaw[(size_t)tok * NSTATE + n] * delta;
    }
    float aL = 1.f, bL = 0.f;
#pragma unroll
    for (int i = 0; i < 8; i++) { bL = fmaf(av[i], bL, bv[i]); aL *= av[i]; }

    __shared__ float sa[256], sbm[256];
    sa[tid] = aL; sbm[tid] = bL;
    __syncthreads();
#pragma unroll
    for (int off = 1; off < 256; off <<= 1) {
        float pa = 1.f, pb = 0.f;
        if (tid >= off) { pa = sa[tid - off]; pb = sbm[tid - off]; }
        float ca = sa[tid], cb2 = sbm[tid];
        __syncthreads();
        sa[tid] = pa * ca;
        sbm[tid] = fmaf(pb, ca, cb2);
        __syncthreads();
    }
    float h = (tid == 0) ? 0.f : sbm[tid - 1];
#pragma unroll
    for (int i = 0; i < 8; i++) {
        h = fmaf(av[i], h, bv[i]);
        g_hs[base + (size_t)(l0 + i) * NSTATE] = h;
    }
}

// ---------------- y = (hs@C^T + D*xc) * silu(gate), 8 tokens/block -----------
#define YM_TB 8
__global__ __launch_bounds__(256) void ymix_kernel(const float* __restrict__ Cmat,
                                                   const float* __restrict__ Dv) {
    int t0 = blockIdx.x * YM_TB;
    __shared__ float hsh[YM_TB][NSTATE];
    if (threadIdx.x < YM_TB * NSTATE) {
        int t = threadIdx.x >> 4, n = threadIdx.x & 15;
        hsh[t][n] = g_hs[(t0 + t) * NSTATE + n];
    }
    __syncthreads();

    for (int d = threadIdx.x; d < DINNER; d += 256) {
        const float4* cr = (const float4*)(Cmat + (size_t)d * NSTATE);
        float4 c0 = cr[0], c1 = cr[1], c2 = cr[2], c3 = cr[3];
        float dvd = Dv[d];
#pragma unroll
        for (int t = 0; t < YM_TB; t++) {
            const float* hh = hsh[t];
            float s = 0.f;
            s = fmaf(hh[0],  c0.x, s); s = fmaf(hh[1],  c0.y, s);
            s = fmaf(hh[2],  c0.z, s); s = fmaf(hh[3],  c0.w, s);
            s = fmaf(hh[4],  c1.x, s); s = fmaf(hh[5],  c1.y, s);
            s = fmaf(hh[6],  c1.z, s); s = fmaf(hh[7],  c1.w, s);
            s = fmaf(hh[8],  c2.x, s); s = fmaf(hh[9],  c2.y, s);
            s = fmaf(hh[10], c2.z, s); s = fmaf(hh[11], c2.w, s);
            s = fmaf(hh[12], c3.x, s); s = fmaf(hh[13], c3.y, s);
            s = fmaf(hh[14], c3.z, s); s = fmaf(hh[15], c3.w, s);
            size_t idx = (size_t)(t0 + t) * DINNER + d;
            float xv = __bfloat162float(g_xcbf[idx]);
            float yv = fmaf(dvd, xv, s);
            float gg = __bfloat162float(g_gatebf[idx]);
            yv *= gg * fsigmoid(gg);
            g_ybf[idx] = __float2bfloat16_rn(yv);
        }
    }
}

// ---------------- launch -----------------------------------------------------
extern "C" void kernel_launch(void* const* d_in, const int* in_sizes, int n_in,
                              void* d_out, int out_size) {
    const float* x       = (const float*)d_in[0];
    const float* ln_g    = (const float*)d_in[1];
    const float* ln_b    = (const float*)d_in[2];
    const float* W_in    = (const float*)d_in[3];
    const float* conv_w  = (const float*)d_in[4];
    const float* conv_b  = (const float*)d_in[5];
    const float* A_log   = (const float*)d_in[6];
    const float* B_mat   = (const float*)d_in[7];
    const float* C_mat   = (const float*)d_in[8];
    const float* D_vec   = (const float*)d_in[9];
    const float* Wd      = (const float*)d_in[10];
    const float* bd      = (const float*)d_in[11];
    const float* W_out   = (const float*)d_in[12];
    float* out           = (float*)d_out;

    __nv_bfloat16 *hbf, *ybf, *wint, *wdt, *woutt, *xcbf;
    cudaGetSymbolAddress((void**)&hbf,   g_hbf);
    cudaGetSymbolAddress((void**)&ybf,   g_ybf);
    cudaGetSymbolAddress((void**)&wint,  g_Wint);
    cudaGetSymbolAddress((void**)&wdt,   g_Wdt);
    cudaGetSymbolAddress((void**)&woutt, g_Woutt);
    cudaGetSymbolAddress((void**)&xcbf,  g_xcbf);

    static cudaStream_t s1 = nullptr, s2 = nullptr;
    static cudaEvent_t e0 = nullptr, e1 = nullptr, e2 = nullptr;
    static bool attr_done = false;
    if (!s1) {
        cudaStreamCreateWithFlags(&s1, cudaStreamNonBlocking);
        cudaStreamCreateWithFlags(&s2, cudaStreamNonBlocking);
        cudaEventCreateWithFlags(&e0, cudaEventDisableTiming);
        cudaEventCreateWithFlags(&e1, cudaEventDisableTiming);
        cudaEventCreateWithFlags(&e2, cudaEventDisableTiming);
    }
    if (!attr_done) {
        cudaFuncSetAttribute(mma_gemm<0>, cudaFuncAttributeMaxDynamicSharedMemorySize, GSMEM_BYTES);
        cudaFuncSetAttribute(mma_gemm<1>, cudaFuncAttributeMaxDynamicSharedMemorySize, GSMEM_BYTES);
        cudaFuncSetAttribute(mma_gemm<2>, cudaFuncAttributeMaxDynamicSharedMemorySize, GSMEM_BYTES);
        attr_done = true;
    }

    // fork
    cudaEventRecord(e0, 0);
    cudaStreamWaitEvent(s1, e0, 0);
    cudaStreamWaitEvent(s2, e0, 0);

    // s1: W_in transpose (GEMM1 dep)
    wtrans_kernel<<<dim3(2 * DINNER / 32, DMODEL / 32), 256, 0, s1>>>(W_in, wint, DMODEL, 2 * DINNER);
    cudaEventRecord(e1, s1);

    // s2: Wd/Wout transpose + B convert (needed by conv_bx/GEMM2/GEMM3)
    prep_kernel<<<WD_TILES + WOUT_TILES + 64, 256, 0, s2>>>(Wd, W_out, B_mat);
    cudaEventRecord(e2, s2);

    // main stream
    ln_kernel<<<NTOK, 256>>>(x, ln_g, ln_b);
    cudaStreamWaitEvent(0, e1, 0);
    // GEMM1: h(4096x1024) @ W_in -> xs | gate (bf16)
    mma_gemm<0><<<dim3(32, 32), 256, GSMEM_BYTES>>>(hbf, wint, nullptr, nullptr, nullptr,
                                                    NTOK, 2 * DINNER, DMODEL);
    cudaStreamWaitEvent(0, e2, 0);          // conv_bx reads g_Bbf (from prep)
    // fused conv + silu + raw B-dots (4 tokens/block)
    conv_bx_kernel<<<NTOK / CB_TB, 256>>>(conv_w, conv_b);
    // GEMM2: xc(4096x2048) @ Wd, softplus row-sum epilogue -> g_dsum
    mma_gemm<1><<<dim3(16, 32), 256, GSMEM_BYTES>>>(xcbf, wdt, nullptr, nullptr, bd,
                                                    NTOK, DINNER, DINNER);
    // scan applies delta + dA inline
    scan_kernel<<<BSZ * NSTATE, 256>>>(A_log);
    ymix_kernel<<<NTOK / YM_TB, 256>>>(C_mat, D_vec);
    // GEMM3: y(4096x2048) @ W_out + residual -> out (fp32)
    mma_gemm<2><<<dim3(8, 32), 256, GSMEM_BYTES>>>(ybf, woutt, out, x, nullptr,
                                                   NTOK, DMODEL, DINNER);
}

// round 17
// speedup vs baseline: 1.1068x; 1.0282x over previous
#include <cuda_runtime.h>
#include <cuda_bf16.h>
#include <math.h>
#include <stdint.h>

#define BSZ     2
#define LSEQ    2048
#define DMODEL  1024
#define DINNER  2048
#define NSTATE  16
#define KCONV   4
#define NTOK    (BSZ*LSEQ)   // 4096

// ---------------- scratch (static device globals; no allocation) -------------
__device__ __align__(256) __nv_bfloat16 g_hbf   [NTOK*DMODEL];
__device__ __align__(256) __nv_bfloat16 g_xsbf  [NTOK*DINNER];
__device__ __align__(256) __nv_bfloat16 g_gatebf[NTOK*DINNER];
__device__ __align__(256) __nv_bfloat16 g_xcbf  [NTOK*DINNER];
__device__ __align__(256) __nv_bfloat16 g_ybf   [NTOK*DINNER];
__device__ __align__(256) __nv_bfloat16 g_Wint  [(2*DINNER)*DMODEL];
__device__ __align__(256) __nv_bfloat16 g_Wdt   [DINNER*DINNER];
__device__ __align__(256) __nv_bfloat16 g_Woutt [DMODEL*DINNER];
__device__ __align__(256) __nv_bfloat16 g_Bbf   [NSTATE*DINNER];
__device__ float g_dsum[NTOK];
__device__ float g_BxRaw[NTOK*NSTATE];
__device__ float g_hs  [NTOK*NSTATE];

// ---------------- helpers ----------------------------------------------------
__device__ __forceinline__ uint32_t smem_u32(const void* p) {
    uint32_t a;
    asm("{ .reg .u64 t; cvta.to.shared.u64 t, %1; cvt.u32.u64 %0, t; }" : "=r"(a) : "l"(p));
    return a;
}
__device__ __forceinline__ void cp16(uint32_t saddr, const void* g) {
    asm volatile("cp.async.cg.shared.global [%0], [%1], 16;" :: "r"(saddr), "l"(g) : "memory");
}
#define CP_COMMIT() asm volatile("cp.async.commit_group;" ::: "memory")

__device__ __forceinline__ void ldsm_x4(uint32_t& r0, uint32_t& r1, uint32_t& r2, uint32_t& r3,
                                        uint32_t addr) {
    asm volatile("ldmatrix.sync.aligned.m8n8.x4.shared.b16 {%0,%1,%2,%3}, [%4];"
                 : "=r"(r0), "=r"(r1), "=r"(r2), "=r"(r3) : "r"(addr));
}
__device__ __forceinline__ void mma_bf16(float& c0, float& c1, float& c2, float& c3,
                                         uint32_t a0, uint32_t a1, uint32_t a2, uint32_t a3,
                                         uint32_t b0, uint32_t b1) {
    asm volatile("mma.sync.aligned.m16n8k16.row.col.f32.bf16.bf16.f32 "
                 "{%0,%1,%2,%3}, {%4,%5,%6,%7}, {%8,%9}, {%0,%1,%2,%3};"
                 : "+f"(c0), "+f"(c1), "+f"(c2), "+f"(c3)
                 : "r"(a0), "r"(a1), "r"(a2), "r"(a3), "r"(b0), "r"(b1));
}
__device__ __forceinline__ float fsigmoid(float v) { return 1.f / (1.f + __expf(-v)); }
__device__ __forceinline__ float fsoftplus(float v) {
    return (v > 20.f) ? v : __logf(1.f + __expf(v));
}

// ---------------- weight transpose tile body ---------------------------------
__device__ __forceinline__ void wtrans_tile(const float* __restrict__ src,
                                            __nv_bfloat16* __restrict__ dst,
                                            int R, int C, int bx, int by) {
    __shared__ float t[32][33];
    int txi = threadIdx.x & 31, tyi = threadIdx.x >> 5;
    int x = bx * 32 + txi;
    int y0 = by * 32;
#pragma unroll
    for (int j = 0; j < 32; j += 8)
        t[tyi + j][txi] = src[(size_t)(y0 + tyi + j) * C + x];
    __syncthreads();
    int xo = by * 32 + txi;
    int yo0 = bx * 32;
#pragma unroll
    for (int j = 0; j < 32; j += 8)
        dst[(size_t)(yo0 + tyi + j) * R + xo] = __float2bfloat16_rn(t[txi][tyi + j]);
}

__global__ __launch_bounds__(256) void wtrans_kernel(const float* __restrict__ src,
                                                     __nv_bfloat16* __restrict__ dst,
                                                     int R, int C) {
    wtrans_tile(src, dst, R, C, blockIdx.x, blockIdx.y);
}

// combined prep: Wd transpose + Wout transpose + bconv
#define WD_TILES   (64 * 64)
#define WOUT_TILES (32 * 64)
__global__ __launch_bounds__(256) void prep_kernel(const float* __restrict__ Wd,
                                                   const float* __restrict__ Wout,
                                                   const float* __restrict__ Bmat) {
    int b = blockIdx.x;
    if (b < WD_TILES) {
        wtrans_tile(Wd, g_Wdt, DINNER, DINNER, b & 63, b >> 6);
    } else if (b < WD_TILES + WOUT_TILES) {
        int bb = b - WD_TILES;
        wtrans_tile(Wout, g_Woutt, DINNER, DMODEL, bb & 31, bb >> 5);
    } else {
        int bb = b - WD_TILES - WOUT_TILES;
        int i = bb * 256 + threadIdx.x;
        float2 v = *(const float2*)(Bmat + 2 * i);
        *(__nv_bfloat162*)(g_Bbf + 2 * i) = __floats2bfloat162_rn(v.x, v.y);
    }
}

// ---------------- layernorm (writes bf16) + zeroes g_dsum --------------------
__global__ __launch_bounds__(256) void ln_kernel(const float* __restrict__ x,
                                                 const float* __restrict__ gamma,
                                                 const float* __restrict__ beta) {
    int row = blockIdx.x;
    if (threadIdx.x == 0) g_dsum[row] = 0.f;
    const float* xr = x + (size_t)row * DMODEL;
    float v[4];
    float s = 0.f, s2 = 0.f;
#pragma unroll
    for (int i = 0; i < 4; i++) {
        v[i] = xr[threadIdx.x + i * 256];
        s  += v[i];
        s2 += v[i] * v[i];
    }
    __shared__ float shs[8], shs2[8];
#pragma unroll
    for (int off = 16; off > 0; off >>= 1) {
        s  += __shfl_xor_sync(0xffffffffu, s,  off);
        s2 += __shfl_xor_sync(0xffffffffu, s2, off);
    }
    int warp = threadIdx.x >> 5, lane = threadIdx.x & 31;
    if (lane == 0) { shs[warp] = s; shs2[warp] = s2; }
    __syncthreads();
    if (threadIdx.x == 0) {
        float a = 0.f, b = 0.f;
#pragma unroll
        for (int w = 0; w < 8; w++) { a += shs[w]; b += shs2[w]; }
        shs[0] = a; shs2[0] = b;
    }
    __syncthreads();
    float mu  = shs[0]  * (1.f / DMODEL);
    float var = shs2[0] * (1.f / DMODEL) - mu * mu;
    float rs  = rsqrtf(var + 1e-5f);
    __nv_bfloat16* hr = g_hbf + (size_t)row * DMODEL;
#pragma unroll
    for (int i = 0; i < 4; i++) {
        int idx = threadIdx.x + i * 256;
        hr[idx] = __float2bfloat16_rn((v[i] - mu) * rs * gamma[idx] + beta[idx]);
    }
}

// ---------------- bf16 mma.sync GEMM, 3-stage pipeline (frozen config) -------
// EPI 0: write bf16 to bdst (explicit destination, no split logic)
// EPI 1: softplus row-sum -> atomicAdd g_dsum
// EPI 2: C0 = acc + extra (fp32 residual)
#define ASTR 72
#define TILE_B (128 * ASTR * 2)
#define GSMEM_BYTES (6 * TILE_B)

template <int EPI>
__global__ __launch_bounds__(256) void mma_gemm(const __nv_bfloat16* __restrict__ A,
                                                const __nv_bfloat16* __restrict__ Bm,
                                                float* __restrict__ C0,
                                                const float* __restrict__ extra,
                                                const float* __restrict__ bias,
                                                __nv_bfloat16* __restrict__ bdst,
                                                int M, int N, int K) {
    extern __shared__ char dsm[];
    uint32_t sb = smem_u32(dsm);

    int tid = threadIdx.x;
    int lane = tid & 31, wid = tid >> 5;
    int warp_m = wid & 1, warp_n = wid >> 1;
    int br = blockIdx.y, bc = blockIdx.x;

    const __nv_bfloat16* Ab = A + (size_t)(br * 128) * K;
    const __nv_bfloat16* Bb = Bm + (size_t)(bc * 128) * K;

    float acc[4][4][4];
#pragma unroll
    for (int mf = 0; mf < 4; mf++)
#pragma unroll
        for (int nf = 0; nf < 4; nf++)
#pragma unroll
            for (int j = 0; j < 4; j++) acc[mf][nf][j] = 0.f;

    int niter = K / 64;

#pragma unroll
    for (int st = 0; st < 2; ++st) {
        uint32_t sa = sb + st * TILE_B;
        uint32_t sbf = sb + (3 + st) * TILE_B;
        int kk = st * 64;
#pragma unroll
        for (int i = 0; i < 4; i++) {
            int idx = tid + i * 256;
            int row = idx >> 3, c = idx & 7;
            cp16(sa + row * (ASTR * 2) + c * 16, Ab + (size_t)row * K + kk + c * 8);
        }
#pragma unroll
        for (int i = 0; i < 4; i++) {
            int idx = tid + i * 256;
            int row = idx >> 3, c = idx & 7;
            cp16(sbf + row * (ASTR * 2) + c * 16, Bb + (size_t)row * K + kk + c * 8);
        }
        CP_COMMIT();
    }

    for (int it = 0; it < niter; ++it) {
        if (it + 2 < niter)
            asm volatile("cp.async.wait_group 1;" ::: "memory");
        else
            asm volatile("cp.async.wait_group 0;" ::: "memory");
        __syncthreads();

        if (it + 2 < niter) {
            int st = (it + 2) % 3;
            uint32_t sa = sb + st * TILE_B;
            uint32_t sbf = sb + (3 + st) * TILE_B;
            int kk = (it + 2) * 64;
#pragma unroll
            for (int i = 0; i < 4; i++) {
                int idx = tid + i * 256;
                int row = idx >> 3, c = idx & 7;
                cp16(sa + row * (ASTR * 2) + c * 16, Ab + (size_t)row * K + kk + c * 8);
            }
#pragma unroll
            for (int i = 0; i < 4; i++) {
                int idx = tid + i * 256;
                int row = idx >> 3, c = idx & 7;
                cp16(sbf + row * (ASTR * 2) + c * 16, Bb + (size_t)row * K + kk + c * 8);
            }
            CP_COMMIT();
        }

        int st = it % 3;
        uint32_t As = sb + st * TILE_B;
        uint32_t Bs = sb + (3 + st) * TILE_B;

#pragma unroll
        for (int ks = 0; ks < 4; ks++) {
            int k0 = ks * 16;
            uint32_t afr[4][4];
#pragma unroll
            for (int mf = 0; mf < 4; mf++) {
                int r = warp_m * 64 + mf * 16 + (lane & 15);
                uint32_t ad = As + (r * ASTR + k0 + (lane >> 4) * 8) * 2;
                ldsm_x4(afr[mf][0], afr[mf][1], afr[mf][2], afr[mf][3], ad);
            }
            uint32_t bfr[4][2];
#pragma unroll
            for (int nfp = 0; nfp < 2; nfp++) {
                int gsel = lane >> 3, rr = lane & 7;
                int n = warp_n * 32 + nfp * 16 + (gsel >> 1) * 8 + rr;
                int ko = k0 + (gsel & 1) * 8;
                uint32_t bd = Bs + (n * ASTR + ko) * 2;
                ldsm_x4(bfr[2 * nfp][0], bfr[2 * nfp][1],
                        bfr[2 * nfp + 1][0], bfr[2 * nfp + 1][1], bd);
            }
#pragma unroll
            for (int mf = 0; mf < 4; mf++)
#pragma unroll
                for (int nf = 0; nf < 4; nf++)
                    mma_bf16(acc[mf][nf][0], acc[mf][nf][1], acc[mf][nf][2], acc[mf][nf][3],
                             afr[mf][0], afr[mf][1], afr[mf][2], afr[mf][3],
                             bfr[nf][0], bfr[nf][1]);
        }
    }

    // -------- epilogue --------
    int g = lane >> 2, t4 = lane & 3;
#pragma unroll
    for (int mf = 0; mf < 4; mf++) {
        int row0 = br * 128 + warp_m * 64 + mf * 16 + g;
        if (EPI == 1) {
            float sum0 = 0.f, sum1 = 0.f;
#pragma unroll
            for (int nf = 0; nf < 4; nf++) {
                int col = bc * 128 + warp_n * 32 + nf * 8 + 2 * t4;
                float b0 = bias[col], b1 = bias[col + 1];
                sum0 += fsoftplus(acc[mf][nf][0] + b0);
                sum0 += fsoftplus(acc[mf][nf][1] + b1);
                sum1 += fsoftplus(acc[mf][nf][2] + b0);
                sum1 += fsoftplus(acc[mf][nf][3] + b1);
            }
#pragma unroll
            for (int off = 1; off < 4; off <<= 1) {
                sum0 += __shfl_xor_sync(0xffffffffu, sum0, off);
                sum1 += __shfl_xor_sync(0xffffffffu, sum1, off);
            }
            if (t4 == 0) {
                atomicAdd(&g_dsum[row0], sum0);
                atomicAdd(&g_dsum[row0 + 8], sum1);
            }
        } else if (EPI == 0) {
            int cbase = bc * 128 + warp_n * 32;
#pragma unroll
            for (int nf = 0; nf < 4; nf++) {
                int col = cbase + nf * 8 + 2 * t4;
                *(__nv_bfloat162*)(bdst + (size_t)row0 * DINNER + col) =
                    __floats2bfloat162_rn(acc[mf][nf][0], acc[mf][nf][1]);
                *(__nv_bfloat162*)(bdst + (size_t)(row0 + 8) * DINNER + col) =
                    __floats2bfloat162_rn(acc[mf][nf][2], acc[mf][nf][3]);
            }
        } else {
#pragma unroll
            for (int nf = 0; nf < 4; nf++) {
                int col = bc * 128 + warp_n * 32 + nf * 8 + 2 * t4;
                float2 e0 = *(const float2*)(extra + (size_t)row0 * N + col);
                float2 e1 = *(const float2*)(extra + (size_t)(row0 + 8) * N + col);
                *(float2*)(C0 + (size_t)row0 * N + col) =
                    make_float2(acc[mf][nf][0] + e0.x, acc[mf][nf][1] + e0.y);
                *(float2*)(C0 + (size_t)(row0 + 8) * N + col) =
                    make_float2(acc[mf][nf][2] + e1.x, acc[mf][nf][3] + e1.y);
            }
        }
    }
}

// ---------------- fused conv+SiLU+B-dot: FOUR tokens per block ---------------
#define CB_TB 4
__global__ __launch_bounds__(256) void conv_bx_kernel(const float* __restrict__ w,
                                                      const float* __restrict__ cb) {
    int t0 = blockIdx.x * CB_TB;
    int b = t0 >> 11, l0 = t0 & (LSEQ - 1);
    int tid = threadIdx.x;
    int d = tid * 8;

    float4 wj[8];
    float cbv[8];
#pragma unroll
    for (int j = 0; j < 8; j++) {
        wj[j] = *(const float4*)(w + (d + j) * KCONV);
        cbv[j] = cb[d + j];
    }

    float xc[CB_TB][8];
#pragma unroll
    for (int tok = 0; tok < CB_TB; tok++) {
        int l = l0 + tok;
        float v[8];
#pragma unroll
        for (int j = 0; j < 8; j++) v[j] = cbv[j];
#pragma unroll
        for (int k = 0; k < KCONV; k++) {
            int ll = l - (KCONV - 1) + k;
            if (ll >= 0) {
                uint4 raw = *(const uint4*)(g_xsbf + ((size_t)(b * LSEQ + ll)) * DINNER + d);
                const __nv_bfloat162* p = (const __nv_bfloat162*)&raw;
#pragma unroll
                for (int j = 0; j < 4; j++) {
                    float2 f = __bfloat1622float2(p[j]);
                    float wk0 = (k == 0) ? wj[2 * j].x : (k == 1) ? wj[2 * j].y : (k == 2) ? wj[2 * j].z : wj[2 * j].w;
                    float wk1 = (k == 0) ? wj[2 * j + 1].x : (k == 1) ? wj[2 * j + 1].y : (k == 2) ? wj[2 * j + 1].z : wj[2 * j + 1].w;
                    v[2 * j]     = fmaf(wk0, f.x, v[2 * j]);
                    v[2 * j + 1] = fmaf(wk1, f.y, v[2 * j + 1]);
                }
            }
        }
        __nv_bfloat16 outv[8];
#pragma unroll
        for (int j = 0; j < 8; j++) {
            float s = v[j] * fsigmoid(v[j]);
            xc[tok][j] = s;
            outv[j] = __float2bfloat16_rn(s);
        }
        *(uint4*)(g_xcbf + (size_t)(t0 + tok) * DINNER + d) = *(uint4*)(outv);
    }

    __shared__ float sh[NSTATE][CB_TB][8];
    int warp = tid >> 5, lane = tid & 31;
#pragma unroll
    for (int n = 0; n < NSTATE; n++) {
        uint4 braw = *(const uint4*)(g_Bbf + n * DINNER + d);
        const __nv_bfloat162* p = (const __nv_bfloat162*)&braw;
        float bf[8];
#pragma unroll
        for (int j = 0; j < 4; j++) {
            float2 f = __bfloat1622float2(p[j]);
            bf[2 * j] = f.x; bf[2 * j + 1] = f.y;
        }
        float part[CB_TB];
#pragma unroll
        for (int tok = 0; tok < CB_TB; tok++) {
            float s = 0.f;
#pragma unroll
            for (int j = 0; j < 8; j++) s = fmaf(xc[tok][j], bf[j], s);
            part[tok] = s;
        }
#pragma unroll
        for (int tok = 0; tok < CB_TB; tok++)
#pragma unroll
            for (int off = 16; off > 0; off >>= 1)
                part[tok] += __shfl_xor_sync(0xffffffffu, part[tok], off);
        if (lane == 0)
#pragma unroll
            for (int tok = 0; tok < CB_TB; tok++) sh[n][tok][warp] = part[tok];
    }
    __syncthreads();
    if (tid < NSTATE * CB_TB) {
        int n = tid & 15, tok = tid >> 4;
        float tot = 0.f;
#pragma unroll
        for (int w8 = 0; w8 < 8; w8++) tot += sh[n][tok][w8];
        g_BxRaw[(size_t)(t0 + tok) * NSTATE + n] = tot;
    }
}

// ---------------- parallel scan; applies delta + dA inline -------------------
__global__ __launch_bounds__(256) void scan_kernel(const float* __restrict__ A_log) {
    int bn = blockIdx.x;
    int b = bn >> 4, n = bn & 15;
    size_t base = (size_t)b * LSEQ * NSTATE + n;
    int tid = threadIdx.x;
    int l0 = tid * 8;
    float An = -expf(A_log[n]);

    float av[8], bv[8];
#pragma unroll
    for (int i = 0; i < 8; i++) {
        int tok = b * LSEQ + l0 + i;
        float delta = g_dsum[tok] * (1.f / DINNER);
        av[i] = __expf(delta * An);
        bv[i] = g_BxRaw[(size_t)tok * NSTATE + n] * delta;
    }
    float aL = 1.f, bL = 0.f;
#pragma unroll
    for (int i = 0; i < 8; i++) { bL = fmaf(av[i], bL, bv[i]); aL *= av[i]; }

    __shared__ float sa[256], sbm[256];
    sa[tid] = aL; sbm[tid] = bL;
    __syncthreads();
#pragma unroll
    for (int off = 1; off < 256; off <<= 1) {
        float pa = 1.f, pb = 0.f;
        if (tid >= off) { pa = sa[tid - off]; pb = sbm[tid - off]; }
        float ca = sa[tid], cb2 = sbm[tid];
        __syncthreads();
        sa[tid] = pa * ca;
        sbm[tid] = fmaf(pb, ca, cb2);
        __syncthreads();
    }
    float h = (tid == 0) ? 0.f : sbm[tid - 1];
#pragma unroll
    for (int i = 0; i < 8; i++) {
        h = fmaf(av[i], h, bv[i]);
        g_hs[base + (size_t)(l0 + i) * NSTATE] = h;
    }
}

// ---------------- y = (hs@C^T + D*xc) * silu(gate), 8 tokens/block -----------
#define YM_TB 8
__global__ __launch_bounds__(256) void ymix_kernel(const float* __restrict__ Cmat,
                                                   const float* __restrict__ Dv) {
    int t0 = blockIdx.x * YM_TB;
    __shared__ float hsh[YM_TB][NSTATE];
    if (threadIdx.x < YM_TB * NSTATE) {
        int t = threadIdx.x >> 4, n = threadIdx.x & 15;
        hsh[t][n] = g_hs[(t0 + t) * NSTATE + n];
    }
    __syncthreads();

    for (int d = threadIdx.x; d < DINNER; d += 256) {
        const float4* cr = (const float4*)(Cmat + (size_t)d * NSTATE);
        float4 c0 = cr[0], c1 = cr[1], c2 = cr[2], c3 = cr[3];
        float dvd = Dv[d];
#pragma unroll
        for (int t = 0; t < YM_TB; t++) {
            const float* hh = hsh[t];
            float s = 0.f;
            s = fmaf(hh[0],  c0.x, s); s = fmaf(hh[1],  c0.y, s);
            s = fmaf(hh[2],  c0.z, s); s = fmaf(hh[3],  c0.w, s);
            s = fmaf(hh[4],  c1.x, s); s = fmaf(hh[5],  c1.y, s);
            s = fmaf(hh[6],  c1.z, s); s = fmaf(hh[7],  c1.w, s);
            s = fmaf(hh[8],  c2.x, s); s = fmaf(hh[9],  c2.y, s);
            s = fmaf(hh[10], c2.z, s); s = fmaf(hh[11], c2.w, s);
            s = fmaf(hh[12], c3.x, s); s = fmaf(hh[13], c3.y, s);
            s = fmaf(hh[14], c3.z, s); s = fmaf(hh[15], c3.w, s);
            size_t idx = (size_t)(t0 + t) * DINNER + d;
            float xv = __bfloat162float(g_xcbf[idx]);
            float yv = fmaf(dvd, xv, s);
            float gg = __bfloat162float(g_gatebf[idx]);
            yv *= gg * fsigmoid(gg);
            g_ybf[idx] = __float2bfloat16_rn(yv);
        }
    }
}

// ---------------- launch -----------------------------------------------------
extern "C" void kernel_launch(void* const* d_in, const int* in_sizes, int n_in,
                              void* d_out, int out_size) {
    const float* x       = (const float*)d_in[0];
    const float* ln_g    = (const float*)d_in[1];
    const float* ln_b    = (const float*)d_in[2];
    const float* W_in    = (const float*)d_in[3];
    const float* conv_w  = (const float*)d_in[4];
    const float* conv_b  = (const float*)d_in[5];
    const float* A_log   = (const float*)d_in[6];
    const float* B_mat   = (const float*)d_in[7];
    const float* C_mat   = (const float*)d_in[8];
    const float* D_vec   = (const float*)d_in[9];
    const float* Wd      = (const float*)d_in[10];
    const float* bd      = (const float*)d_in[11];
    const float* W_out   = (const float*)d_in[12];
    float* out           = (float*)d_out;

    __nv_bfloat16 *hbf, *ybf, *wint, *wdt, *woutt, *xcbf, *xsbf, *gatebf;
    cudaGetSymbolAddress((void**)&hbf,    g_hbf);
    cudaGetSymbolAddress((void**)&ybf,    g_ybf);
    cudaGetSymbolAddress((void**)&wint,   g_Wint);
    cudaGetSymbolAddress((void**)&wdt,    g_Wdt);
    cudaGetSymbolAddress((void**)&woutt,  g_Woutt);
    cudaGetSymbolAddress((void**)&xcbf,   g_xcbf);
    cudaGetSymbolAddress((void**)&xsbf,   g_xsbf);
    cudaGetSymbolAddress((void**)&gatebf, g_gatebf);

    static cudaStream_t s1 = nullptr, s2 = nullptr, s3 = nullptr;   // s3: low priority
    static cudaEvent_t ev[5] = {};
    static bool attr_done = false;
    if (!s1) {
        cudaStreamCreateWithFlags(&s1, cudaStreamNonBlocking);
        cudaStreamCreateWithFlags(&s2, cudaStreamNonBlocking);
        int leastP = 0, greatestP = 0;
        cudaDeviceGetStreamPriorityRange(&leastP, &greatestP);
        cudaStreamCreateWithPriority(&s3, cudaStreamNonBlocking, leastP);
        for (int i = 0; i < 5; i++) cudaEventCreateWithFlags(&ev[i], cudaEventDisableTiming);
    }
    if (!attr_done) {
        cudaFuncSetAttribute(mma_gemm<0>, cudaFuncAttributeMaxDynamicSharedMemorySize, GSMEM_BYTES);
        cudaFuncSetAttribute(mma_gemm<1>, cudaFuncAttributeMaxDynamicSharedMemorySize, GSMEM_BYTES);
        cudaFuncSetAttribute(mma_gemm<2>, cudaFuncAttributeMaxDynamicSharedMemorySize, GSMEM_BYTES);
        attr_done = true;
    }

    // fork
    cudaEventRecord(ev[0], 0);
    cudaStreamWaitEvent(s1, ev[0], 0);
    cudaStreamWaitEvent(s2, ev[0], 0);
    cudaStreamWaitEvent(s3, ev[0], 0);

    // s1: W_in transpose (dep of both GEMM1 halves)
    wtrans_kernel<<<dim3(2 * DINNER / 32, DMODEL / 32), 256, 0, s1>>>(W_in, wint, DMODEL, 2 * DINNER);
    cudaEventRecord(ev[1], s1);

    // s2: Wd/Wout transpose + B convert
    prep_kernel<<<WD_TILES + WOUT_TILES + 64, 256, 0, s2>>>(Wd, W_out, B_mat);
    cudaEventRecord(ev[2], s2);

    // main stream: ln (produces hbf)
    ln_kernel<<<NTOK, 256>>>(x, ln_g, ln_b);
    cudaEventRecord(ev[3], 0);               // hbf ready

    // s3 (LOW priority): gate half of GEMM1 — only needed by ymix, backfills idle slots
    cudaStreamWaitEvent(s3, ev[1], 0);
    cudaStreamWaitEvent(s3, ev[3], 0);
    mma_gemm<0><<<dim3(16, 32), 256, GSMEM_BYTES, s3>>>(hbf, wint + (size_t)DINNER * DMODEL,
                                                        nullptr, nullptr, nullptr, gatebf,
                                                        NTOK, DINNER, DMODEL);
    cudaEventRecord(ev[4], s3);

    // main: xs half of GEMM1 (critical path)
    cudaStreamWaitEvent(0, ev[1], 0);
    mma_gemm<0><<<dim3(16, 32), 256, GSMEM_BYTES>>>(hbf, wint, nullptr, nullptr, nullptr, xsbf,
                                                    NTOK, DINNER, DMODEL);
    cudaStreamWaitEvent(0, ev[2], 0);        // conv_bx reads g_Bbf
    conv_bx_kernel<<<NTOK / CB_TB, 256>>>(conv_w, conv_b);
    mma_gemm<1><<<dim3(16, 32), 256, GSMEM_BYTES>>>(xcbf, wdt, nullptr, nullptr, bd, nullptr,
                                                    NTOK, DINNER, DINNER);
    scan_kernel<<<BSZ * NSTATE, 256>>>(A_log);
    cudaStreamWaitEvent(0, ev[4], 0);        // gate must be ready before ymix
    ymix_kernel<<<NTOK / YM_TB, 256>>>(C_mat, D_vec);
    mma_gemm<2><<<dim3(8, 32), 256, GSMEM_BYTES>>>(ybf, woutt, out, x, nullptr, nullptr,
                                                   NTOK, DMODEL, DINNER);
}